// round 15
// baseline (speedup 1.0000x reference)
#include <cuda_runtime.h>

// ---------------------------------------------------------------------------
// AutoregressiveGRUWithAttention  (B=1024, L=64, T=128, IN=13, H=64, OUT=13)
//
// R14 = R13 (2 rows/thread, Wfusion = Wih@Wf fused gi, 2 syncs/step) +
// SOFTWARE PIPELINING across two batch groups (4+4): each phase runs
//   A(group g)  [register-row GEMVs, fma-heavy]  concurrently with
//   B(group 1-g)[gate nonlinearities + online softmax, latency-heavy]
// so the fma stream hides the transcendental chain. Same barrier count.
//   Roles: tid 0-95: Whh rows (tid,tid+96) on h | 96-191: Wfusion rows on o
//          192-223: Wa rows (r,r+32) on o       | 224-255: Wf row on o -> y
//   B ownership: thread owns (batch 0+bb, j) [group 0] and (4+bb, j) [grp 1].
// Online-softmax attention == reference masked softmax (validated R7-R13).
// ---------------------------------------------------------------------------

typedef unsigned long long ull;

namespace {
constexpr int L_ = 64, T_ = 128, IN_ = 13, H_ = 64, OUT_ = 13, NB_ = 8;
constexpr int THREADS_ = 256, BLOCKS_ = 128;
constexpr int HS_ = 68;              // state row stride
constexpr int GP_ = NB_ * HS_;       // 544 floats per gate plane
constexpr int XT_ = 16, XPB_ = L_ * XT_;
constexpr int WIHS_ = 17;            // Wih smem stride (conflict-free)

constexpr int SM_SH  = 0;                   // h   [8][68]
constexpr int SM_SO  = SM_SH  + GP_;        // o   [8][68]
constexpr int SM_GH  = SM_SO  + GP_;        // Whh.h  [3][8][68]
constexpr int SM_GF  = SM_GH  + 3 * GP_;    // Wfus.o [3][8][68]
constexpr int SM_LG  = SM_GF  + 3 * GP_;    // logits [8][68]
constexpr int SM_BFX = SM_LG  + GP_;        // Wih.bf [192]
constexpr int SM_WIH = SM_BFX + 192;        // [192][17]
constexpr int SM_SX  = SM_WIH + 192 * WIHS_ + 15;  // x [8][1024]
constexpr int SM_FLOATS = SM_SX + NB_ * XPB_;
constexpr int SMEM_BYTES = SM_FLOATS * 4;
}

__device__ __forceinline__ ull fma2_(ull a, ull b, ull c) {
    ull d;
    asm("fma.rn.f32x2 %0, %1, %2, %3;" : "=l"(d) : "l"(a), "l"(b), "l"(c));
    return d;
}
__device__ __forceinline__ float hsum2_(ull a) {
    unsigned lo, hi;
    asm("mov.b64 {%0, %1}, %2;" : "=r"(lo), "=r"(hi) : "l"(a));
    return __uint_as_float(lo) + __uint_as_float(hi);
}
__device__ __forceinline__ ull pack2_(float lo, float hi) {
    ull d;
    asm("mov.b64 %0, {%1, %2};" : "=l"(d) : "r"(__float_as_uint(lo)), "r"(__float_as_uint(hi)));
    return d;
}
__device__ __forceinline__ float sigmoid_(float a) {
    return __fdividef(1.f, 1.f + __expf(-a));
}
__device__ __forceinline__ float tanh_(float a) {
    float c  = fminf(fmaxf(a, -15.f), 15.f);
    float e2 = __expf(2.f * c);
    return __fdividef(e2 - 1.f, e2 + 1.f);
}

// Two register rows dotted with the 4 state vectors of group g.
__device__ __forceinline__ void dots4_r2(const ull (&w)[64], const float* src,
                                         int g, float* dA, float* dB) {
    #pragma unroll
    for (int bi = 0; bi < 4; bi += 2) {
        const int b = 4 * g + bi;
        const float* p0 = src + b * HS_;
        const float* p1 = src + (b + 1) * HS_;
        ull a0 = 0, a1 = 0, c0 = 0, c1 = 0;
        #pragma unroll
        for (int c = 0; c < 16; ++c) {
            ulonglong2 v0 = *(const ulonglong2*)(p0 + 4 * c);
            ulonglong2 v1 = *(const ulonglong2*)(p1 + 4 * c);
            a0 = fma2_(w[2*c],    v0.x, a0); a0 = fma2_(w[2*c+1],    v0.y, a0);
            a1 = fma2_(w[2*c],    v1.x, a1); a1 = fma2_(w[2*c+1],    v1.y, a1);
            c0 = fma2_(w[32+2*c], v0.x, c0); c0 = fma2_(w[32+2*c+1], v0.y, c0);
            c1 = fma2_(w[32+2*c], v1.x, c1); c1 = fma2_(w[32+2*c+1], v1.y, c1);
        }
        dA[b * HS_]       = hsum2_(a0);
        dA[(b + 1) * HS_] = hsum2_(a1);
        dB[b * HS_]       = hsum2_(c0);
        dB[(b + 1) * HS_] = hsum2_(c1);
    }
}

// One register row dotted with group g's 4 state vectors -> y4.
__device__ __forceinline__ void dots4_r1(const ull* w, const float* src,
                                         int g, float (&y4)[4]) {
    #pragma unroll
    for (int bi = 0; bi < 4; bi += 2) {
        const int b = 4 * g + bi;
        const float* p0 = src + b * HS_;
        const float* p1 = src + (b + 1) * HS_;
        ull a0 = 0, a1 = 0;
        #pragma unroll
        for (int c = 0; c < 16; ++c) {
            ulonglong2 v0 = *(const ulonglong2*)(p0 + 4 * c);
            ulonglong2 v1 = *(const ulonglong2*)(p1 + 4 * c);
            a0 = fma2_(w[2*c], v0.x, a0); a0 = fma2_(w[2*c+1], v0.y, a0);
            a1 = fma2_(w[2*c], v1.x, a1); a1 = fma2_(w[2*c+1], v1.y, a1);
        }
        y4[bi]     = hsum2_(a0);
        y4[bi + 1] = hsum2_(a1);
    }
}

__global__ void __launch_bounds__(THREADS_, 1)
gru_attn_kernel(const float* __restrict__ x, const int* __restrict__ lengths,
                const float* __restrict__ Wih, const float* __restrict__ Whh,
                const float* __restrict__ bih, const float* __restrict__ bhh,
                const float* __restrict__ Wf,  const float* __restrict__ bf,
                const float* __restrict__ Wa,  const float* __restrict__ ba,
                float* __restrict__ out)
{
    extern __shared__ float sm[];
    float* sh   = sm + SM_SH;
    float* so   = sm + SM_SO;
    float* gh   = sm + SM_GH;
    float* gf   = sm + SM_GF;
    float* slg  = sm + SM_LG;
    float* sbfx = sm + SM_BFX;
    float* sWih = sm + SM_WIH;
    float* sx   = sm + SM_SX;
    __shared__ int smax;

    const int tid = threadIdx.x;
    const int b0  = blockIdx.x * NB_;
    const int j2  = tid & 63;
    const int bb  = tid >> 6;                 // 0..3
    const int offg[2] = { bb * HS_ + j2, (4 + bb) * HS_ + j2 };

    // ---- prologue staging
    for (int idx = tid; idx < NB_ * XPB_; idx += THREADS_) {
        int b = idx >> 10, r = idx & 1023, tt = r >> 4, i = r & 15;
        sx[idx] = (i < IN_) ? x[(size_t)(b0 + b) * (L_ * IN_) + tt * IN_ + i] : 0.f;
    }
    for (int idx = tid; idx < 192 * IN_; idx += THREADS_) {
        int r = idx / IN_, i = idx - r * IN_;
        sWih[r * WIHS_ + i] = Wih[idx];
    }
    for (int idx = tid; idx < GP_; idx += THREADS_) sh[idx] = 0.f;
    if (tid == 0) {
        int m = 0;
        #pragma unroll
        for (int b = 0; b < NB_; ++b) m = max(m, lengths[b0 + b]);
        smax = m;
    }

    // ---- per-role register rows + destinations
    ull w2[64];
    float bf_reg = 0.f;
    float* dA = gh;
    float* dB = gh;

    if (tid < 96) {                       // Whh rows (tid, tid+96), src = sh
        const ull* p = (const ull*)(Whh + tid * H_);
        #pragma unroll
        for (int k = 0; k < 32; ++k) w2[k] = p[k];
        p = (const ull*)(Whh + (tid + 96) * H_);
        #pragma unroll
        for (int k = 0; k < 32; ++k) w2[32 + k] = p[k];
        dA = gh + (tid >> 6) * GP_ + (tid & 63);
        dB = gh + ((tid + 96) >> 6) * GP_ + ((tid + 96) & 63);
    } else if (tid < 192) {               // Wfusion rows (tid-96, tid), src = so
        const int r0 = tid - 96, r1 = tid;
        float wA[13], wB[13];
        #pragma unroll
        for (int i = 0; i < IN_; ++i) { wA[i] = Wih[r0 * IN_ + i]; wB[i] = Wih[r1 * IN_ + i]; }
        float bxA = 0.f, bxB = 0.f;
        #pragma unroll
        for (int i = 0; i < IN_; ++i) { bxA += wA[i] * bf[i]; bxB += wB[i] * bf[i]; }
        sbfx[r0] = bxA; sbfx[r1] = bxB;
        #pragma unroll
        for (int k = 0; k < 32; ++k) {
            float a0 = 0.f, a1 = 0.f, b0v = 0.f, b1v = 0.f;
            #pragma unroll
            for (int i = 0; i < IN_; ++i) {
                float f0 = Wf[i * H_ + 2 * k], f1 = Wf[i * H_ + 2 * k + 1];
                a0  += wA[i] * f0;  a1  += wA[i] * f1;
                b0v += wB[i] * f0;  b1v += wB[i] * f1;
            }
            w2[k]      = pack2_(a0, a1);
            w2[32 + k] = pack2_(b0v, b1v);
        }
        dA = gf + (r0 >> 6) * GP_ + (r0 & 63);
        dB = gf + (r1 >> 6) * GP_ + (r1 & 63);
    } else if (tid < 224) {               // Wa rows (r0, r0+32), src = so
        const int r0 = tid - 192;
        const ull* p = (const ull*)(Wa + r0 * H_);
        #pragma unroll
        for (int k = 0; k < 32; ++k) w2[k] = p[k];
        p = (const ull*)(Wa + (r0 + 32) * H_);
        #pragma unroll
        for (int k = 0; k < 32; ++k) w2[32 + k] = p[k];
        dA = slg + r0;
        dB = slg + r0 + 32;
    } else {                              // Wf row, src = so
        const int oc = min(tid - 224, OUT_ - 1);
        const ull* p = (const ull*)(Wf + oc * H_);
        #pragma unroll
        for (int k = 0; k < 32; ++k) { w2[k] = p[k]; w2[32 + k] = 0; }
        bf_reg = bf[oc];
    }
    const bool wf_ok = (tid >= 224) && (tid - 224 < OUT_);
    const int  wf_oc = tid - 224;

    // ---- Phase-B constants
    const float brr = bih[j2]          + bhh[j2];
    const float bzz = bih[H_ + j2]     + bhh[H_ + j2];
    const float bni = bih[2 * H_ + j2];
    const float bnh = bhh[2 * H_ + j2];
    const float bav = ba[j2];
    const int len_[2] = { lengths[b0 + bb], lengths[b0 + bb + 4] };

    __syncthreads();
    const int Lmax = smax;
    const float bfxr = sbfx[j2];
    const float bfxz = sbfx[H_ + j2];
    const float bfxn = sbfx[2 * H_ + j2];

    float h_own[2] = {0.f, 0.f};
    float gi_r[2], gi_z[2], gi_n[2];

    // gi (Wih . x[tt]) for this thread's group-g pair
    auto compute_gi = [&](int g, int tt) {
        float r = 0.f, z = 0.f, n = 0.f;
        const float* xa = sx + (4 * g + bb) * XPB_ + tt * XT_;
        #pragma unroll
        for (int i = 0; i < IN_; ++i) {
            float va = xa[i];
            r += sWih[j2 * WIHS_ + i] * va;
            z += sWih[(64 + j2) * WIHS_ + i] * va;
            n += sWih[(128 + j2) * WIHS_ + i] * va;
        }
        gi_r[g] = r; gi_z[g] = z; gi_n[g] = n;
    };

    // encoder B for group g at time t
    auto B_enc = [&](int g, int t) {
        const int off = offg[g];
        float r = sigmoid_(gh[off] + gi_r[g] + brr);
        float z = sigmoid_(gh[GP_ + off] + gi_z[g] + bzz);
        float n = tanh_((gi_n[g] + bni) + r * (gh[2 * GP_ + off] + bnh));
        float hne = (1.f - z) * n + z * h_own[g];
        h_own[g] = (t < len_[g]) ? hne : h_own[g];
        sh[off] = h_own[g];
    };

    // =======================  ENCODER (pipelined)  =======================
    compute_gi(0, 0);
    compute_gi(1, 0);
    if (tid < 96) dots4_r2(w2, sh, 0, dA, dB);
    __syncthreads();
    for (int t = 0; t < Lmax; ++t) {
        // phase: A_1(t) + B_0(t)
        if (tid < 96) dots4_r2(w2, sh, 1, dA, dB);
        B_enc(0, t);
        compute_gi(0, (t + 1 < Lmax) ? t + 1 : t);
        __syncthreads();
        // phase: A_0(t+1) + B_1(t)   (A_0(Lmax) is unused garbage, harmless)
        if (tid < 96) dots4_r2(w2, sh, 0, dA, dB);
        B_enc(1, t);
        compute_gi(1, (t + 1 < Lmax) ? t + 1 : t);
        __syncthreads();
    }

    // o_init = outs[-1]: nonzero only when length == L
    so[offg[0]] = (len_[0] == L_) ? h_own[0] : 0.f;
    so[offg[1]] = (len_[1] == L_) ? h_own[1] : 0.f;
    __syncthreads();

    // =======================  DECODER (pipelined)  =======================
    float m_[2] = {-1e30f, -1e30f}, s_[2] = {0.f, 0.f};
    float a_[2] = {0.f, 0.f}, op_[2] = {0.f, 0.f};

    // decoder A for group g at time t (y(t-1) emitted when t>0)
    auto A_dec = [&](int g, int t) {
        if (tid < 96) {
            dots4_r2(w2, sh, g, dA, dB);
        } else if (tid < 224) {
            dots4_r2(w2, so, g, dA, dB);
        } else {
            float y4[4];
            dots4_r1(w2, so, g, y4);
            if (t > 0 && wf_ok) {
                #pragma unroll
                for (int bi = 0; bi < 4; ++bi)
                    out[((size_t)(b0 + 4 * g + bi) * T_ + (t - 1)) * OUT_ + wf_oc] =
                        y4[bi] + bf_reg;
            }
        }
    };
    // decoder B for group g at time t
    auto B_dec = [&](int g, int t) {
        const int off = offg[g];
        float l = slg[off] + bav;               // logit of o(t-1)
        if (t > 0) {                            // fold buf[t-1] = o(t-1)
            float mn = fmaxf(m_[g], l);
            float c = __expf(m_[g] - mn), e = __expf(l - mn);
            s_[g] = s_[g] * c + e;  a_[g] = a_[g] * c + e * op_[g];  m_[g] = mn;
        }
        float r = sigmoid_(gh[off] + gf[off] + brr + bfxr);
        float z = sigmoid_(gh[GP_ + off] + gf[GP_ + off] + bzz + bfxz);
        float n = tanh_((gf[2 * GP_ + off] + bni + bfxn) +
                        r * (gh[2 * GP_ + off] + bnh));
        float hne = (1.f - z) * n + z * h_own[g];
        float att = (t == 0) ? 0.f : __fdividef(a_[g], s_[g]);
        float ov = hne + att;
        h_own[g] = hne;  op_[g] = ov;
        sh[off] = hne;   so[off] = ov;
    };

    A_dec(0, 0);                 // prologue
    __syncthreads();
    for (int t = 0; t < T_; ++t) {
        A_dec(1, t);  B_dec(0, t);
        __syncthreads();
        A_dec(0, t + 1);  B_dec(1, t);   // A_0(T) emits y(T-1) for group 0
        __syncthreads();
    }
    A_dec(1, T_);                // drain: y(T-1) for group 1
}

extern "C" void kernel_launch(void* const* d_in, const int* in_sizes, int n_in,
                              void* d_out, int out_size) {
    const float* xp   = nullptr;
    const int*   lenp = nullptr;
    const float *Wihp = nullptr, *Whhp = nullptr, *bihp = nullptr, *bhhp = nullptr;
    const float *Wfp = nullptr, *bfp = nullptr, *Wap = nullptr, *bap = nullptr;

    for (int i = 0; i < n_in; ++i) {
        switch (in_sizes[i]) {
            case 1024 * 64 * 13: xp   = (const float*)d_in[i]; break;
            case 1024:           lenp = (const int*)d_in[i];   break;
            case 192 * 13:       Wihp = (const float*)d_in[i]; break;
            case 192 * 64:       Whhp = (const float*)d_in[i]; break;
            case 192:
                if (!bihp) bihp = (const float*)d_in[i];
                else       bhhp = (const float*)d_in[i];
                break;
            case 13 * 64:        Wfp  = (const float*)d_in[i]; break;
            case 13:             bfp  = (const float*)d_in[i]; break;
            case 64 * 64:        Wap  = (const float*)d_in[i]; break;
            case 64:             bap  = (const float*)d_in[i]; break;
            default: break;   // output_length scalar -> T=128 hardcoded
        }
    }

    cudaFuncSetAttribute(gru_attn_kernel,
                         cudaFuncAttributeMaxDynamicSharedMemorySize, SMEM_BYTES);

    gru_attn_kernel<<<BLOCKS_, THREADS_, SMEM_BYTES>>>(
        xp, lenp, Wihp, Whhp, bihp, bhhp, Wfp, bfp, Wap, bap, (float*)d_out);
}